// round 7
// baseline (speedup 1.0000x reference)
#include <cuda_runtime.h>
#include <cstdint>

#define NB   8192
#define ND   1024
#define NE   32
#define NA   128
#define NBNA (NB * NA)

// ---------------- device-global scratch (no allocs) ----------------
__device__ float g_weights[NB * NE];
__device__ float g_part[2 * NBNA];
__device__ float g_xr[NB * ND];           // tf32-rounded, k-interleaved x
__device__ float g_wr[NE * NA * ND];      // tf32-rounded, k-interleaved W_strat

// ---------------- helpers ----------------
__device__ __forceinline__ uint32_t smem_u32(const void* p) {
    uint32_t a;
    asm("{ .reg .u64 t; cvta.to.shared.u64 t, %1; cvt.u32.u64 %0, t; }" : "=r"(a) : "l"(p));
    return a;
}
__device__ __forceinline__ void cp16(uint32_t dst, const void* src) {
    asm volatile("cp.async.cg.shared.global [%0], [%1], 16;" :: "r"(dst), "l"(src) : "memory");
}
#define CP_COMMIT() asm volatile("cp.async.commit_group;" ::: "memory")
template <int N> __device__ __forceinline__ void cp_wait() {
    asm volatile("cp.async.wait_group %0;" :: "n"(N) : "memory");
}
__device__ __forceinline__ float tf32r(float f) {
    uint32_t r; asm("cvt.rna.tf32.f32 %0, %1;" : "=r"(r) : "f"(f));
    return __uint_as_float(r);
}
__device__ __forceinline__ void mma8f(float* d, float2 a01, float2 a23, float2 b) {
    asm volatile("mma.sync.aligned.m16n8k8.row.col.f32.tf32.tf32.f32 "
                 "{%0,%1,%2,%3}, {%4,%5,%6,%7}, {%8,%9}, {%0,%1,%2,%3};"
                 : "+f"(d[0]), "+f"(d[1]), "+f"(d[2]), "+f"(d[3])
                 : "r"(__float_as_uint(a01.x)), "r"(__float_as_uint(a23.x)),
                   "r"(__float_as_uint(a01.y)), "r"(__float_as_uint(a23.y)),
                   "r"(__float_as_uint(b.x)),   "r"(__float_as_uint(b.y)));
}

// smem geometry (floats): BK=64, row stride 68, 3 stages
#define TSTR   68
#define TILEF  (128 * TSTR)              // 8704 floats = 34816 B per tile
#define STAGEF (2 * TILEF)               // x + W per stage
#define WSMF   (3 * STAGEF)              // w_sm at 52224 floats
#define SMEM_STRAT ((WSMF + 16 * 128) * 4)   // 217088 B

// ============================================================================
// Kernel 0: tf32-round + k-interleave (within each 8-group: [0,4,1,5,2,6,3,7])
// ============================================================================
__global__ void __launch_bounds__(256)
round_kernel(const float* __restrict__ src, float* __restrict__ dst, int n8) {
    int i = blockIdx.x * blockDim.x + threadIdx.x;
    if (i < n8) {
        float4 lo = ((const float4*)src)[2 * i];
        float4 hi = ((const float4*)src)[2 * i + 1];
        float4 o0 = make_float4(tf32r(lo.x), tf32r(hi.x), tf32r(lo.y), tf32r(hi.y));
        float4 o1 = make_float4(tf32r(lo.z), tf32r(hi.z), tf32r(lo.w), tf32r(hi.w));
        ((float4*)dst)[2 * i]     = o0;
        ((float4*)dst)[2 * i + 1] = o1;
    }
}

// ============================================================================
// Kernel 1: gating (full fp32) — 16 rows/block, smem-staged W_att
// ============================================================================
__global__ void __launch_bounds__(256)
gate_kernel(const float* __restrict__ x,  const float* __restrict__ Watt,
            const float* __restrict__ batt, const float* __restrict__ abias,
            const float* __restrict__ gum) {
    __shared__ float Wsm[NE * 64];
    __shared__ float red[8 * 33 * 32];

    const int tid  = threadIdx.x;
    const int lane = tid & 31;
    const int wid  = tid >> 5;
    const int r0   = blockIdx.x * 16 + wid * 2;
    const int r1   = r0 + 1;

    float la[NE], lb[NE];
#pragma unroll
    for (int e = 0; e < NE; ++e) { la[e] = 0.f; lb[e] = 0.f; }

    for (int kt = 0; kt < 16; ++kt) {
        __syncthreads();
#pragma unroll
        for (int p = 0; p < 4; ++p) {
            int idx = tid + 256 * p;
            int e = idx >> 5, k2 = idx & 31;
            *(float2*)&Wsm[e * 64 + k2 * 2] =
                *(const float2*)&Watt[(size_t)e * ND + kt * 64 + k2 * 2];
        }
        __syncthreads();
        float2 xa = *(const float2*)&x[(size_t)r0 * ND + kt * 64 + lane * 2];
        float2 xb = *(const float2*)&x[(size_t)r1 * ND + kt * 64 + lane * 2];
#pragma unroll
        for (int e = 0; e < NE; ++e) {
            float2 wv = *(const float2*)&Wsm[e * 64 + lane * 2];
            la[e] = fmaf(xa.x, wv.x, fmaf(xa.y, wv.y, la[e]));
            lb[e] = fmaf(xb.x, wv.x, fmaf(xb.y, wv.y, lb[e]));
        }
    }

    float* pr = &red[wid * 33 * 32];
#pragma unroll
    for (int half = 0; half < 2; ++half) {
        float* src = half ? lb : la;
        int row = half ? r1 : r0;
#pragma unroll
        for (int e = 0; e < NE; ++e) pr[lane * 33 + e] = src[e];
        __syncwarp();
        float logit = 0.f;
#pragma unroll
        for (int l = 0; l < 32; ++l) logit += pr[l * 33 + lane];
        logit += batt[lane] + abias[lane];
        float u = gum[row * NE + lane];
        logit += -logf(-logf(u + 1e-10f) + 1e-10f);
        float mx = logit;
#pragma unroll
        for (int o = 16; o > 0; o >>= 1) mx = fmaxf(mx, __shfl_xor_sync(0xffffffffu, mx, o));
        float p = expf(logit - mx);
        float s = p;
#pragma unroll
        for (int o = 16; o > 0; o >>= 1) s += __shfl_xor_sync(0xffffffffu, s, o);
        g_weights[row * NE + lane] = p / s;
        __syncwarp();
    }
}

// ============================================================================
// Kernel 2: fused superposition GEMM — BK=64, 3-stage cp.async, 1 barrier/iter
// ============================================================================
__device__ __forceinline__ void load_xw64(const float* __restrict__ xr,
                                          const float* __restrict__ wr,
                                          int m0, int eidx, int kt,
                                          uint32_t xs, uint32_t ws, int tid) {
    const float* xsrc = xr + (size_t)m0 * ND + kt * 64;
    const float* wsrc = wr + (size_t)eidx * NA * ND + kt * 64;
#pragma unroll
    for (int p = 0; p < 8; ++p) {
        int idx = tid + 256 * p;
        int r = idx >> 4, c = idx & 15;
        cp16(xs + (r * TSTR + c * 4) * 4, xsrc + (size_t)r * ND + c * 4);
    }
#pragma unroll
    for (int p = 0; p < 8; ++p) {
        int idx = tid + 256 * p;
        int r = idx >> 4, c = idx & 15;
        cp16(ws + (r * TSTR + c * 4) * 4, wsrc + (size_t)r * ND + c * 4);
    }
}

__global__ void __launch_bounds__(256, 1)
strat_mma_kernel(const float* __restrict__ xr, const float* __restrict__ wr) {
    extern __shared__ char dynsm[];
    float* smf = (float*)dynsm;
    const uint32_t smb = smem_u32(dynsm);
    const int tid    = threadIdx.x;
    const int lane   = tid & 31;
    const int wid    = tid >> 5;
    const int warp_m = wid & 1;
    const int warp_n = wid >> 1;
    const int g      = lane >> 2;
    const int c      = lane & 3;
    const int m0     = blockIdx.x * 128;
    const int z      = blockIdx.y;
    const int ebase  = z * 16;

    float* w_sm = smf + WSMF;                 // [e][m] : 16 x 128
#pragma unroll
    for (int p = 0; p < 8; ++p) {
        int idx = tid + 256 * p;              // e = idx>>7, m = idx&127
        w_sm[idx] = g_weights[(size_t)(m0 + (idx & 127)) * NE + ebase + (idx >> 7)];
    }

    float acc[4][4][4];
#pragma unroll
    for (int tm = 0; tm < 4; ++tm)
#pragma unroll
        for (int tn = 0; tn < 4; ++tn)
#pragma unroll
            for (int q = 0; q < 4; ++q) acc[tm][tn][q] = 0.f;
    float part[4][4][4];

    // prologue: stages for it=0,1
    load_xw64(xr, wr, m0, ebase, 0, smb, smb + TILEF * 4, tid);
    CP_COMMIT();
    load_xw64(xr, wr, m0, ebase, 1,
              smb + STAGEF * 4, smb + (STAGEF + TILEF) * 4, tid);
    CP_COMMIT();

    int s = 0;                                // current stage slot
    for (int it = 0; it < 256; ++it) {
        const int kt = it & 15;
        cp_wait<1>();
        __syncthreads();

        const float* xsf = smf + s * STAGEF;
        const float* wsf = xsf + TILEF;

        if (kt == 0) {
#pragma unroll
            for (int tm = 0; tm < 4; ++tm)
#pragma unroll
                for (int tn = 0; tn < 4; ++tn)
#pragma unroll
                    for (int q = 0; q < 4; ++q) part[tm][tn][q] = 0.f;
        }

#pragma unroll
        for (int ks = 0; ks < 8; ++ks) {
            const int ko = ks * 8 + 2 * c;
            float2 a01[4], a23[4], bf[4];
#pragma unroll
            for (int tm = 0; tm < 4; ++tm) {
                const int row = warp_m * 64 + tm * 16 + g;
                a01[tm] = *(const float2*)(xsf + row * TSTR + ko);
                a23[tm] = *(const float2*)(xsf + (row + 8) * TSTR + ko);
            }
#pragma unroll
            for (int tn = 0; tn < 4; ++tn) {
                const int row = warp_n * 32 + tn * 8 + g;
                bf[tn] = *(const float2*)(wsf + row * TSTR + ko);
            }
#pragma unroll
            for (int tm = 0; tm < 4; ++tm)
#pragma unroll
                for (int tn = 0; tn < 4; ++tn)
                    mma8f(part[tm][tn], a01[tm], a23[tm], bf[tn]);
        }

        if (kt == 15) {                       // fold expert with gating weight
            const int e = it >> 4;
#pragma unroll
            for (int tm = 0; tm < 4; ++tm) {
                float wlo = w_sm[e * 128 + warp_m * 64 + tm * 16 + g];
                float whi = w_sm[e * 128 + warp_m * 64 + tm * 16 + g + 8];
#pragma unroll
                for (int tn = 0; tn < 4; ++tn) {
                    acc[tm][tn][0] = fmaf(wlo, part[tm][tn][0], acc[tm][tn][0]);
                    acc[tm][tn][1] = fmaf(wlo, part[tm][tn][1], acc[tm][tn][1]);
                    acc[tm][tn][2] = fmaf(whi, part[tm][tn][2], acc[tm][tn][2]);
                    acc[tm][tn][3] = fmaf(whi, part[tm][tn][3], acc[tm][tn][3]);
                }
            }
        }

        // issue load for it+2 into slot (s+2)%3 (holds stage it-1, barrier-safe)
        const int nit = it + 2;
        if (nit < 256) {
            int ns = s + 2; if (ns >= 3) ns -= 3;
            load_xw64(xr, wr, m0, ebase + (nit >> 4), nit & 15,
                      smb + ns * STAGEF * 4, smb + (ns * STAGEF + TILEF) * 4, tid);
        }
        CP_COMMIT();

        if (++s == 3) s = 0;
    }

    // epilogue: half-partial -> g_part[z]
    float* dst = g_part + (size_t)z * NBNA;
#pragma unroll
    for (int tm = 0; tm < 4; ++tm) {
        const int row = m0 + warp_m * 64 + tm * 16 + g;
#pragma unroll
        for (int tn = 0; tn < 4; ++tn) {
            const int col = warp_n * 32 + tn * 8 + 2 * c;
            *(float2*)&dst[(size_t)row * NA + col] =
                make_float2(acc[tm][tn][0], acc[tm][tn][1]);
            *(float2*)&dst[(size_t)(row + 8) * NA + col] =
                make_float2(acc[tm][tn][2], acc[tm][tn][3]);
        }
    }
}

// ============================================================================
// Kernel 3: sum halves + weighted bias
// ============================================================================
__global__ void __launch_bounds__(256)
reduce_kernel(const float* __restrict__ bstrat, float* __restrict__ out) {
    __shared__ float bs[NE * NA];
    __shared__ float wsh[8 * NE];
    const int tid = threadIdx.x;
    const int b0  = blockIdx.x * 8;
#pragma unroll
    for (int p = 0; p < 16; ++p) bs[tid + 256 * p] = bstrat[tid + 256 * p];
    wsh[tid] = g_weights[(size_t)b0 * NE + tid];
    __syncthreads();

    const int row = tid >> 5;
    const int n4  = (tid & 31) * 4;
    const size_t b = b0 + row;
    float4 a  = *(const float4*)&g_part[b * NA + n4];
    float4 p1 = *(const float4*)&g_part[NBNA + b * NA + n4];
    a.x += p1.x; a.y += p1.y; a.z += p1.z; a.w += p1.w;
#pragma unroll
    for (int e = 0; e < NE; ++e) {
        float w = wsh[row * NE + e];
        float4 bv = *(const float4*)&bs[e * NA + n4];
        a.x = fmaf(w, bv.x, a.x);
        a.y = fmaf(w, bv.y, a.y);
        a.z = fmaf(w, bv.z, a.z);
        a.w = fmaf(w, bv.w, a.w);
    }
    *(float4*)&out[b * NA + n4] = a;
}

// ============================================================================
extern "C" void kernel_launch(void* const* d_in, const int* in_sizes, int n_in,
                              void* d_out, int out_size) {
    const float* x      = (const float*)d_in[0];
    const float* Watt   = (const float*)d_in[1];
    const float* batt   = (const float*)d_in[2];
    const float* abias  = (const float*)d_in[3];
    const float* Wstrat = (const float*)d_in[4];
    const float* bstrat = (const float*)d_in[5];
    const float* gum    = (const float*)d_in[6];
    float* out          = (float*)d_out;

    gate_kernel<<<NB / 16, 256>>>(x, Watt, batt, abias, gum);

    float* xr = nullptr; float* wrp = nullptr;
    cudaGetSymbolAddress((void**)&xr,  g_xr);
    cudaGetSymbolAddress((void**)&wrp, g_wr);
    round_kernel<<<(NB * ND / 8 + 255) / 256, 256>>>(x, xr, NB * ND / 8);
    round_kernel<<<(NE * NA * ND / 8 + 255) / 256, 256>>>(Wstrat, wrp, NE * NA * ND / 8);

    cudaFuncSetAttribute(strat_mma_kernel,
                         cudaFuncAttributeMaxDynamicSharedMemorySize, SMEM_STRAT);
    strat_mma_kernel<<<dim3(NB / 128, 2), 256, SMEM_STRAT>>>(xr, wrp);

    reduce_kernel<<<NB / 8, 256>>>(bstrat, out);
}

// round 9
// speedup vs baseline: 2.2638x; 2.2638x over previous
#include <cuda_runtime.h>
#include <cuda_fp16.h>
#include <cstdint>

#define NB   8192
#define ND   1024
#define NE   32
#define NA   128
#define NBNA (NB * NA)

// ---------------- device-global scratch (no allocs) ----------------
__device__ float  g_weights[NB * NE];
__device__ float  g_part[2 * NBNA];
__device__ __half g_xh[NB * ND];          // fp16, k-interleaved x
__device__ __half g_wh[NE * NA * ND];     // fp16, k-interleaved W_strat

// ---------------- helpers ----------------
__device__ __forceinline__ uint32_t smem_u32(const void* p) {
    uint32_t a;
    asm("{ .reg .u64 t; cvta.to.shared.u64 t, %1; cvt.u32.u64 %0, t; }" : "=r"(a) : "l"(p));
    return a;
}
__device__ __forceinline__ void cp16(uint32_t dst, const void* src) {
    asm volatile("cp.async.cg.shared.global [%0], [%1], 16;" :: "r"(dst), "l"(src) : "memory");
}
#define CP_COMMIT() asm volatile("cp.async.commit_group;" ::: "memory")
template <int N> __device__ __forceinline__ void cp_wait() {
    asm volatile("cp.async.wait_group %0;" :: "n"(N) : "memory");
}
__device__ __forceinline__ void mma16f(float* d, uint32_t a0, uint32_t a1,
                                       uint32_t a2, uint32_t a3,
                                       uint32_t b0, uint32_t b1) {
    asm volatile("mma.sync.aligned.m16n8k16.row.col.f32.f16.f16.f32 "
                 "{%0,%1,%2,%3}, {%4,%5,%6,%7}, {%8,%9}, {%0,%1,%2,%3};"
                 : "+f"(d[0]), "+f"(d[1]), "+f"(d[2]), "+f"(d[3])
                 : "r"(a0), "r"(a1), "r"(a2), "r"(a3), "r"(b0), "r"(b1));
}

// smem geometry (bytes): BK=64 halves, row stride 80 halves = 160 B, 3 stages
#define TSTRB  160
#define TILEB  (128 * TSTRB)             // 20480 B per tile
#define STAGEB (2 * TILEB)               // x + W per stage
#define WSMO   (3 * STAGEB)              // 122880; w_sm floats after stages
#define SMEM_STRAT (WSMO + 16 * 128 * 4) // 131072 B

// ============================================================================
// Kernel 0: fp32 -> fp16 (rne) + k16-interleave [0,1,8,9, 2,3,10,11, ...]
// ============================================================================
__global__ void __launch_bounds__(256)
round_h_kernel(const float* __restrict__ src, __half* __restrict__ dst, int n16) {
    int i = blockIdx.x * blockDim.x + threadIdx.x;
    if (i < n16) {
        const float4* s = (const float4*)src + 4 * (size_t)i;
        float4 v0 = s[0], v1 = s[1], v2 = s[2], v3 = s[3];
        __half2 h[8];
        h[0] = __floats2half2_rn(v0.x, v0.y);   // k0,k1
        h[1] = __floats2half2_rn(v2.x, v2.y);   // k8,k9
        h[2] = __floats2half2_rn(v0.z, v0.w);   // k2,k3
        h[3] = __floats2half2_rn(v2.z, v2.w);   // k10,k11
        h[4] = __floats2half2_rn(v1.x, v1.y);   // k4,k5
        h[5] = __floats2half2_rn(v3.x, v3.y);   // k12,k13
        h[6] = __floats2half2_rn(v1.z, v1.w);   // k6,k7
        h[7] = __floats2half2_rn(v3.z, v3.w);   // k14,k15
        uint4* d = (uint4*)(dst + 16 * (size_t)i);
        d[0] = *(uint4*)&h[0];
        d[1] = *(uint4*)&h[4];
    }
}

// ============================================================================
// Kernel 1: gating (full fp32) — 16 rows/block, smem-staged W_att
// ============================================================================
__global__ void __launch_bounds__(256)
gate_kernel(const float* __restrict__ x,  const float* __restrict__ Watt,
            const float* __restrict__ batt, const float* __restrict__ abias,
            const float* __restrict__ gum) {
    __shared__ float Wsm[NE * 64];
    __shared__ float red[8 * 33 * 32];

    const int tid  = threadIdx.x;
    const int lane = tid & 31;
    const int wid  = tid >> 5;
    const int r0   = blockIdx.x * 16 + wid * 2;
    const int r1   = r0 + 1;

    float la[NE], lb[NE];
#pragma unroll
    for (int e = 0; e < NE; ++e) { la[e] = 0.f; lb[e] = 0.f; }

    for (int kt = 0; kt < 16; ++kt) {
        __syncthreads();
#pragma unroll
        for (int p = 0; p < 4; ++p) {
            int idx = tid + 256 * p;
            int e = idx >> 5, k2 = idx & 31;
            *(float2*)&Wsm[e * 64 + k2 * 2] =
                *(const float2*)&Watt[(size_t)e * ND + kt * 64 + k2 * 2];
        }
        __syncthreads();
        float2 xa = *(const float2*)&x[(size_t)r0 * ND + kt * 64 + lane * 2];
        float2 xb = *(const float2*)&x[(size_t)r1 * ND + kt * 64 + lane * 2];
#pragma unroll
        for (int e = 0; e < NE; ++e) {
            float2 wv = *(const float2*)&Wsm[e * 64 + lane * 2];
            la[e] = fmaf(xa.x, wv.x, fmaf(xa.y, wv.y, la[e]));
            lb[e] = fmaf(xb.x, wv.x, fmaf(xb.y, wv.y, lb[e]));
        }
    }

    float* pr = &red[wid * 33 * 32];
#pragma unroll
    for (int half = 0; half < 2; ++half) {
        float* src = half ? lb : la;
        int row = half ? r1 : r0;
#pragma unroll
        for (int e = 0; e < NE; ++e) pr[lane * 33 + e] = src[e];
        __syncwarp();
        float logit = 0.f;
#pragma unroll
        for (int l = 0; l < 32; ++l) logit += pr[l * 33 + lane];
        logit += batt[lane] + abias[lane];
        float u = gum[row * NE + lane];
        logit += -logf(-logf(u + 1e-10f) + 1e-10f);
        float mx = logit;
#pragma unroll
        for (int o = 16; o > 0; o >>= 1) mx = fmaxf(mx, __shfl_xor_sync(0xffffffffu, mx, o));
        float p = expf(logit - mx);
        float s = p;
#pragma unroll
        for (int o = 16; o > 0; o >>= 1) s += __shfl_xor_sync(0xffffffffu, s, o);
        g_weights[row * NE + lane] = p / s;
        __syncwarp();
    }
}

// ============================================================================
// Kernel 2: fused superposition GEMM — fp16 m16n8k16, 3-stage cp.async ring
// ============================================================================
__device__ __forceinline__ void load_xw64h(const __half* __restrict__ xh,
                                           const __half* __restrict__ wh,
                                           int m0, int eidx, int kt,
                                           uint32_t xs, uint32_t ws, int tid) {
    const __half* xsrc = xh + (size_t)m0 * ND + kt * 64;
    const __half* wsrc = wh + (size_t)eidx * NA * ND + kt * 64;
#pragma unroll
    for (int p = 0; p < 4; ++p) {
        int idx = tid + 256 * p;             // 0..1023
        int r = idx >> 3, c = idx & 7;
        cp16(xs + r * TSTRB + c * 16, xsrc + (size_t)r * ND + c * 8);
    }
#pragma unroll
    for (int p = 0; p < 4; ++p) {
        int idx = tid + 256 * p;
        int r = idx >> 3, c = idx & 7;
        cp16(ws + r * TSTRB + c * 16, wsrc + (size_t)r * ND + c * 8);
    }
}

__global__ void __launch_bounds__(256, 1)
strat_mma_kernel(const __half* __restrict__ xh, const __half* __restrict__ wh) {
    extern __shared__ char dynsm[];
    const uint32_t smb = smem_u32(dynsm);
    const int tid    = threadIdx.x;
    const int lane   = tid & 31;
    const int wid    = tid >> 5;
    const int warp_m = wid & 1;
    const int warp_n = wid >> 1;
    const int g      = lane >> 2;
    const int c      = lane & 3;
    const int m0     = blockIdx.x * 128;
    const int z      = blockIdx.y;
    const int ebase  = z * 16;

    float* w_sm = (float*)(dynsm + WSMO);     // [e][m] : 16 x 128
#pragma unroll
    for (int p = 0; p < 8; ++p) {
        int idx = tid + 256 * p;              // e = idx>>7, m = idx&127
        w_sm[idx] = g_weights[(size_t)(m0 + (idx & 127)) * NE + ebase + (idx >> 7)];
    }

    float acc[4][4][4];
#pragma unroll
    for (int tm = 0; tm < 4; ++tm)
#pragma unroll
        for (int tn = 0; tn < 4; ++tn)
#pragma unroll
            for (int q = 0; q < 4; ++q) acc[tm][tn][q] = 0.f;
    float part[4][4][4];

    // prologue: stages for it=0,1
    load_xw64h(xh, wh, m0, ebase, 0, smb, smb + TILEB, tid);
    CP_COMMIT();
    load_xw64h(xh, wh, m0, ebase, 1, smb + STAGEB, smb + STAGEB + TILEB, tid);
    CP_COMMIT();

    int s = 0;
    for (int it = 0; it < 256; ++it) {
        const int kt = it & 15;
        cp_wait<1>();
        __syncthreads();

        const char* xsf = dynsm + s * STAGEB;
        const char* wsf = xsf + TILEB;

        if (kt == 0) {
#pragma unroll
            for (int tm = 0; tm < 4; ++tm)
#pragma unroll
                for (int tn = 0; tn < 4; ++tn)
#pragma unroll
                    for (int q = 0; q < 4; ++q) part[tm][tn][q] = 0.f;
        }

#pragma unroll
        for (int ks = 0; ks < 4; ++ks) {
            const int ko = ks * 32 + c * 8;   // byte offset within row
            uint2 alo[4], ahi[4], bu[4];
#pragma unroll
            for (int tm = 0; tm < 4; ++tm) {
                const int row = warp_m * 64 + tm * 16 + g;
                alo[tm] = *(const uint2*)(xsf + row * TSTRB + ko);        // a0,a2
                ahi[tm] = *(const uint2*)(xsf + (row + 8) * TSTRB + ko);  // a1,a3
            }
#pragma unroll
            for (int tn = 0; tn < 4; ++tn) {
                const int row = warp_n * 32 + tn * 8 + g;
                bu[tn] = *(const uint2*)(wsf + row * TSTRB + ko);         // b0,b1
            }
#pragma unroll
            for (int tm = 0; tm < 4; ++tm)
#pragma unroll
                for (int tn = 0; tn < 4; ++tn)
                    mma16f(part[tm][tn], alo[tm].x, ahi[tm].x, alo[tm].y, ahi[tm].y,
                           bu[tn].x, bu[tn].y);
        }

        if (kt == 15) {                       // fold expert with gating weight
            const int e = it >> 4;
#pragma unroll
            for (int tm = 0; tm < 4; ++tm) {
                float wlo = w_sm[e * 128 + warp_m * 64 + tm * 16 + g];
                float whi = w_sm[e * 128 + warp_m * 64 + tm * 16 + g + 8];
#pragma unroll
                for (int tn = 0; tn < 4; ++tn) {
                    acc[tm][tn][0] = fmaf(wlo, part[tm][tn][0], acc[tm][tn][0]);
                    acc[tm][tn][1] = fmaf(wlo, part[tm][tn][1], acc[tm][tn][1]);
                    acc[tm][tn][2] = fmaf(whi, part[tm][tn][2], acc[tm][tn][2]);
                    acc[tm][tn][3] = fmaf(whi, part[tm][tn][3], acc[tm][tn][3]);
                }
            }
        }

        // issue load for it+2 into slot (s+2)%3 (holds stage it-1, barrier-safe)
        const int nit = it + 2;
        if (nit < 256) {
            int ns = s + 2; if (ns >= 3) ns -= 3;
            load_xw64h(xh, wh, m0, ebase + (nit >> 4), nit & 15,
                       smb + ns * STAGEB, smb + ns * STAGEB + TILEB, tid);
        }
        CP_COMMIT();

        if (++s == 3) s = 0;
    }

    // epilogue: half-partial -> g_part[z]
    float* dst = g_part + (size_t)z * NBNA;
#pragma unroll
    for (int tm = 0; tm < 4; ++tm) {
        const int row = m0 + warp_m * 64 + tm * 16 + g;
#pragma unroll
        for (int tn = 0; tn < 4; ++tn) {
            const int col = warp_n * 32 + tn * 8 + 2 * c;
            *(float2*)&dst[(size_t)row * NA + col] =
                make_float2(acc[tm][tn][0], acc[tm][tn][1]);
            *(float2*)&dst[(size_t)(row + 8) * NA + col] =
                make_float2(acc[tm][tn][2], acc[tm][tn][3]);
        }
    }
}

// ============================================================================
// Kernel 3: sum halves + weighted bias
// ============================================================================
__global__ void __launch_bounds__(256)
reduce_kernel(const float* __restrict__ bstrat, float* __restrict__ out) {
    __shared__ float bs[NE * NA];
    __shared__ float wsh[8 * NE];
    const int tid = threadIdx.x;
    const int b0  = blockIdx.x * 8;
#pragma unroll
    for (int p = 0; p < 16; ++p) bs[tid + 256 * p] = bstrat[tid + 256 * p];
    wsh[tid] = g_weights[(size_t)b0 * NE + tid];
    __syncthreads();

    const int row = tid >> 5;
    const int n4  = (tid & 31) * 4;
    const size_t b = b0 + row;
    float4 a  = *(const float4*)&g_part[b * NA + n4];
    float4 p1 = *(const float4*)&g_part[NBNA + b * NA + n4];
    a.x += p1.x; a.y += p1.y; a.z += p1.z; a.w += p1.w;
#pragma unroll
    for (int e = 0; e < NE; ++e) {
        float w = wsh[row * NE + e];
        float4 bv = *(const float4*)&bs[e * NA + n4];
        a.x = fmaf(w, bv.x, a.x);
        a.y = fmaf(w, bv.y, a.y);
        a.z = fmaf(w, bv.z, a.z);
        a.w = fmaf(w, bv.w, a.w);
    }
    *(float4*)&out[b * NA + n4] = a;
}

// ============================================================================
extern "C" void kernel_launch(void* const* d_in, const int* in_sizes, int n_in,
                              void* d_out, int out_size) {
    const float* x      = (const float*)d_in[0];
    const float* Watt   = (const float*)d_in[1];
    const float* batt   = (const float*)d_in[2];
    const float* abias  = (const float*)d_in[3];
    const float* Wstrat = (const float*)d_in[4];
    const float* bstrat = (const float*)d_in[5];
    const float* gum    = (const float*)d_in[6];
    float* out          = (float*)d_out;

    gate_kernel<<<NB / 16, 256>>>(x, Watt, batt, abias, gum);

    __half* xh = nullptr; __half* wh = nullptr;
    cudaGetSymbolAddress((void**)&xh, g_xh);
    cudaGetSymbolAddress((void**)&wh, g_wh);
    round_h_kernel<<<(NB * ND / 16 + 255) / 256, 256>>>(x, xh, NB * ND / 16);
    round_h_kernel<<<(NE * NA * ND / 16 + 255) / 256, 256>>>(Wstrat, wh, NE * NA * ND / 16);

    cudaFuncSetAttribute(strat_mma_kernel,
                         cudaFuncAttributeMaxDynamicSharedMemorySize, SMEM_STRAT);
    strat_mma_kernel<<<dim3(NB / 128, 2), 256, SMEM_STRAT>>>(xh, wh);

    reduce_kernel<<<NB / 8, 256>>>(bstrat, out);
}